// round 2
// baseline (speedup 1.0000x reference)
#include <cuda_runtime.h>
#include <math.h>

// ---------------------------------------------------------------------------
// VectorQuantizerLinearSoft: fused fp32 implementation
//   latents [65536, 256] fp32, embedding [1024, 256] fp32
// Outputs (flattened fp32, reference return order):
//   quantized[B*D], vq_loss, entropy, hard_idx[B], hard_quant[B*D],
//   probs[B*K], cluster_metric
// ---------------------------------------------------------------------------

constexpr int NB = 65536;
constexpr int ND = 256;
constexpr int NK = 1024;
constexpr int BM = 32;               // rows per CTA
constexpr int NCTA = NB / BM;        // 2048

constexpr size_t OFF_Q   = 0;
constexpr size_t OFF_VQ  = 16777216;
constexpr size_t OFF_ENT = 16777217;
constexpr size_t OFF_IDX = 16777218;
constexpr size_t OFF_HQ  = 16842754;   // float-offset % 4 == 2  -> only 8B aligned!
constexpr size_t OFF_P   = 33619970;
constexpr size_t OFF_CM  = 100728834;

// Scratch (device globals: no allocations allowed)
__device__ float g_eT[ND * NK];          // embedding transposed [d][c], 1MB
__device__ float g_ee[NK];               // ||e_j||^2
__device__ float g_pavg[NCTA * NK];      // per-CTA column sums of probs (8MB)
__device__ float g_pavg2[32 * NK];       // stage-2 partials
__device__ float g_ploss[NCTA];          // per-CTA sum of (q-z)^2
__device__ float g_pmind[NCTA];          // per-CTA sum of min dist

// ---------------- cp.async helpers ----------------
__device__ __forceinline__ void cp16(void* smem, const void* gmem) {
    unsigned s = (unsigned)__cvta_generic_to_shared(smem);
    asm volatile("cp.async.cg.shared.global [%0], [%1], 16;\n" :: "r"(s), "l"(gmem));
}
__device__ __forceinline__ void cp_commit() { asm volatile("cp.async.commit_group;\n"); }
__device__ __forceinline__ void cp_wait1()  { asm volatile("cp.async.wait_group 1;\n"); }
__device__ __forceinline__ void cp_wait0()  { asm volatile("cp.async.wait_group 0;\n"); }

// ---------------- prep: transpose embedding -> g_eT ----------------
__global__ void k_prep(const float* __restrict__ emb) {
    __shared__ float t[32][33];
    int c0 = blockIdx.x * 32, d0 = blockIdx.y * 32;
    int x = threadIdx.x, y = threadIdx.y;
#pragma unroll
    for (int i = 0; i < 4; ++i) {
        int c = c0 + y + 8 * i;
        t[y + 8 * i][x] = emb[(size_t)c * ND + d0 + x];
    }
    __syncthreads();
#pragma unroll
    for (int i = 0; i < 4; ++i) {
        int d = d0 + y + 8 * i;
        g_eT[(size_t)d * NK + c0 + x] = t[x][y + 8 * i];
    }
}

// ---------------- prep: embedding row norms ----------------
__global__ void k_ee(const float* __restrict__ emb) {
    int warp = (blockIdx.x * blockDim.x + threadIdx.x) >> 5;  // 0..31
    int lane = threadIdx.x & 31;
    for (int rr = 0; rr < 32; ++rr) {
        int row = warp * 32 + rr;
        float s = 0.f;
#pragma unroll
        for (int k = 0; k < 8; ++k) {
            float v = emb[(size_t)row * ND + lane + 32 * k];
            s = fmaf(v, v, s);
        }
#pragma unroll
        for (int off = 16; off; off >>= 1) s += __shfl_xor_sync(0xffffffffu, s, off);
        if (lane == 0) g_ee[row] = s;
    }
}

// ---------------- main fused kernel ----------------
// smem layout (floats):
//   [0, 32768)      GEMM1 eT double buffer (2 x 16x1024)  -> later probs P[32][1024]
//   [32768, 40960)  z tile [32][256]
//   [40960, 57344)  warp colsums [8][1024] -> later GEMM2 e double buffer (2 x 32x256)
__global__ void __launch_bounds__(256, 1)
k_main(const float* __restrict__ lat, const float* __restrict__ emb,
       float* __restrict__ out) {
    extern __shared__ float sm[];
    float* sP  = sm;
    float* sZ  = sm + 32768;
    float* sX  = sm + 40960;   // colsum / GEMM2 buffers

    __shared__ float s_zz[BM];
    __shared__ float s_mind[BM];
    __shared__ int   s_idx[BM];
    __shared__ float s_red[8];

    const int cta  = blockIdx.x;
    const int row0 = cta * BM;
    const int tid  = threadIdx.x;
    const int w    = tid >> 5;
    const int lane = tid & 31;

    // ---- prefetch GEMM1 chunk 0 (eT rows 0..15, 64KB) ----
    {
        const float* src = g_eT;
        float* dst = sm;  // buffer 0
        for (int i = tid; i < 4096; i += 256) cp16(dst + i * 4, src + i * 4);
        cp_commit();
    }

    // ---- load z tile ----
    for (int i = tid; i < BM * ND / 4; i += 256)
        ((float4*)sZ)[i] = ((const float4*)(lat + (size_t)row0 * ND))[i];
    __syncthreads();

    // ---- zz per row ----
#pragma unroll
    for (int i = 0; i < 4; ++i) {
        int r = w * 4 + i;
        float s = 0.f;
#pragma unroll
        for (int k = 0; k < 8; ++k) {
            float v = sZ[r * ND + lane + 32 * k];
            s = fmaf(v, v, s);
        }
#pragma unroll
        for (int off = 16; off; off >>= 1) s += __shfl_xor_sync(0xffffffffu, s, off);
        if (lane == 0) s_zz[r] = s;
    }

    // ---- GEMM1: acc[i][j] = z[4w+i] . e[lane+32j] ----
    float acc[4][32];
#pragma unroll
    for (int i = 0; i < 4; ++i)
#pragma unroll
        for (int j = 0; j < 32; ++j) acc[i][j] = 0.f;

#pragma unroll 1
    for (int ch = 0; ch < 16; ++ch) {
        if (ch < 15) {
            const float* src = g_eT + (size_t)(ch + 1) * 16 * NK;
            float* dst = sm + ((ch + 1) & 1) * 16384;
            for (int i = tid; i < 4096; i += 256) cp16(dst + i * 4, src + i * 4);
            cp_commit();
            cp_wait1();
        } else {
            cp_wait0();
        }
        __syncthreads();

        const float* bufp = sm + (ch & 1) * 16384;
        const float* zrow = sZ + (w * 4) * ND + ch * 16;
#pragma unroll 4
        for (int kk = 0; kk < 16; ++kk) {
            float z0 = zrow[kk];
            float z1 = zrow[256 + kk];
            float z2 = zrow[512 + kk];
            float z3 = zrow[768 + kk];
            const float* er = bufp + kk * NK + lane;
#pragma unroll
            for (int j = 0; j < 32; ++j) {
                float ev = er[j * 32];
                acc[0][j] = fmaf(z0, ev, acc[0][j]);
                acc[1][j] = fmaf(z1, ev, acc[1][j]);
                acc[2][j] = fmaf(z2, ev, acc[2][j]);
                acc[3][j] = fmaf(z3, ev, acc[3][j]);
            }
        }
        __syncthreads();
    }

    // ---- dist, argmin, softmax; write probs to smem + gmem ----
    // Replicate reference elementwise ops exactly: t = zz + ee; dist = t - 2*g
#pragma unroll
    for (int i = 0; i < 4; ++i) {
        int r = w * 4 + i;
        float zz = s_zz[r];
        float dmin = 3.4e38f;
        int imin = NK;
#pragma unroll
        for (int j = 0; j < 32; ++j) {
            float ee = __ldg(&g_ee[lane + 32 * j]);
            float di = __fsub_rn(__fadd_rn(zz, ee), __fmul_rn(2.0f, acc[i][j]));
            acc[i][j] = di;
            int col = lane + 32 * j;
            if (di < dmin) { dmin = di; imin = col; }   // cols ascending -> first min
        }
#pragma unroll
        for (int off = 16; off; off >>= 1) {
            float od = __shfl_xor_sync(0xffffffffu, dmin, off);
            int   oi = __shfl_xor_sync(0xffffffffu, imin, off);
            if (od < dmin || (od == dmin && oi < imin)) { dmin = od; imin = oi; }
        }
        if (lane == 0) { s_mind[r] = dmin; s_idx[r] = imin; }

        float ssum = 0.f;
#pragma unroll
        for (int j = 0; j < 32; ++j) {
            float pv = __expf(-10.0f * (acc[i][j] - dmin));
            acc[i][j] = pv;
            ssum += pv;
        }
#pragma unroll
        for (int off = 16; off; off >>= 1) ssum += __shfl_xor_sync(0xffffffffu, ssum, off);
        float rinv = 1.0f / ssum;
        float* pout = out + OFF_P + (size_t)(row0 + r) * NK;
#pragma unroll
        for (int j = 0; j < 32; ++j) {
            float p = acc[i][j] * rinv;
            acc[i][j] = p;
            sP[r * NK + lane + 32 * j] = p;
            pout[lane + 32 * j] = p;
        }
    }

    // ---- per-warp column sums (for avg_probs) ----
#pragma unroll
    for (int j = 0; j < 32; ++j) {
        float cs = acc[0][j] + acc[1][j] + acc[2][j] + acc[3][j];
        sX[w * NK + lane + 32 * j] = cs;
    }
    __syncthreads();

    for (int c = tid; c < NK; c += 256) {
        float s = 0.f;
#pragma unroll
        for (int ww = 0; ww < 8; ++ww) s += sX[ww * NK + c];
        g_pavg[(size_t)cta * NK + c] = s;
    }

    // min-dist partial + hard index output
    if (tid == 0) {
        float s = 0.f;
        for (int r = 0; r < BM; ++r) s += s_mind[r];
        g_pmind[cta] = s;
    }
    if (tid < BM) out[OFF_IDX + row0 + tid] = (float)s_idx[tid];

    // hard quantized = embedding[idx]  -- float2: OFF_HQ is only 8B-aligned
    for (int i = tid; i < BM * ND / 2; i += 256) {
        int r = i >> 7, d2 = i & 127;
        float2 v = ((const float2*)(emb + (size_t)s_idx[r] * ND))[d2];
        ((float2*)(out + OFF_HQ + (size_t)row0 * ND))[i] = v;
    }
    __syncthreads();  // sX (colsums) consumed before GEMM2 buffers reuse it

    // ---- GEMM2: q = P @ emb ----
    float qacc[4][8];
#pragma unroll
    for (int i = 0; i < 4; ++i)
#pragma unroll
        for (int m = 0; m < 8; ++m) qacc[i][m] = 0.f;

    {   // prefetch chunk 0 (emb rows 0..31, 32KB)
        const float* src = emb;
        float* dst = sX;
        for (int i = tid; i < 2048; i += 256) cp16(dst + i * 4, src + i * 4);
        cp_commit();
    }

#pragma unroll 1
    for (int ch = 0; ch < 32; ++ch) {
        if (ch < 31) {
            const float* src = emb + (size_t)(ch + 1) * 32 * ND;
            float* dst = sX + ((ch + 1) & 1) * 8192;
            for (int i = tid; i < 2048; i += 256) cp16(dst + i * 4, src + i * 4);
            cp_commit();
            cp_wait1();
        } else {
            cp_wait0();
        }
        __syncthreads();

        const float* bp   = sX + (ch & 1) * 8192;
        const float* prow = sP + (w * 4) * NK + ch * 32;
#pragma unroll 4
        for (int c = 0; c < 32; ++c) {
            float p0 = prow[c];
            float p1 = prow[NK + c];
            float p2 = prow[2 * NK + c];
            float p3 = prow[3 * NK + c];
            const float* er = bp + c * ND + lane;
#pragma unroll
            for (int m = 0; m < 8; ++m) {
                float ev = er[32 * m];
                qacc[0][m] = fmaf(p0, ev, qacc[0][m]);
                qacc[1][m] = fmaf(p1, ev, qacc[1][m]);
                qacc[2][m] = fmaf(p2, ev, qacc[2][m]);
                qacc[3][m] = fmaf(p3, ev, qacc[3][m]);
            }
        }
        __syncthreads();
    }

    // ---- write q, accumulate loss ----
    float lp = 0.f;
#pragma unroll
    for (int i = 0; i < 4; ++i) {
        int r = w * 4 + i;
        float* qout = out + OFF_Q + (size_t)(row0 + r) * ND;
#pragma unroll
        for (int m = 0; m < 8; ++m) {
            int d = lane + 32 * m;
            float qv = qacc[i][m];
            qout[d] = qv;
            float dz = qv - sZ[r * ND + d];
            lp = fmaf(dz, dz, lp);
        }
    }
#pragma unroll
    for (int off = 16; off; off >>= 1) lp += __shfl_xor_sync(0xffffffffu, lp, off);
    if (lane == 0) s_red[w] = lp;
    __syncthreads();
    if (tid == 0) {
        float s = 0.f;
        for (int ww = 0; ww < 8; ++ww) s += s_red[ww];
        g_ploss[cta] = s;
    }
}

// ---------------- stage-2 avg_probs reduction ----------------
__global__ void k_red() {
    int g = blockIdx.x;  // 0..31
    for (int c = threadIdx.x; c < NK; c += 256) {
        float s = 0.f;
        for (int r = 0; r < 64; ++r) s += g_pavg[(size_t)(g * 64 + r) * NK + c];
        g_pavg2[g * NK + c] = s;
    }
}

// ---------------- finalize scalars ----------------
__global__ void k_fin(float* __restrict__ out) {
    __shared__ float red[1024];
    int t = threadIdx.x;

    // entropy
    float a = 0.f;
    for (int gg = 0; gg < 32; ++gg) a += g_pavg2[gg * NK + t];
    a *= (1.0f / 65536.0f);
    red[t] = -a * logf(a + 1e-10f);
    __syncthreads();
    for (int s = 512; s; s >>= 1) { if (t < s) red[t] += red[t + s]; __syncthreads(); }
    float ent = red[0];
    __syncthreads();

    // vq loss
    red[t] = g_ploss[t] + g_ploss[t + 1024];
    __syncthreads();
    for (int s = 512; s; s >>= 1) { if (t < s) red[t] += red[t + s]; __syncthreads(); }
    float mse = red[0] * (1.0f / 16777216.0f);
    float vq  = __fadd_rn(__fmul_rn(mse, 0.25f), mse);
    __syncthreads();

    // cluster metric
    red[t] = g_pmind[t] + g_pmind[t + 1024];
    __syncthreads();
    for (int s = 512; s; s >>= 1) { if (t < s) red[t] += red[t + s]; __syncthreads(); }
    float cm = red[0] * (1.0f / 65536.0f);

    if (t == 0) {
        out[OFF_VQ]  = vq;
        out[OFF_ENT] = ent;
        out[OFF_CM]  = cm;
    }
}

// ---------------- launch ----------------
extern "C" void kernel_launch(void* const* d_in, const int* in_sizes, int n_in,
                              void* d_out, int out_size) {
    const float* lat = (const float*)d_in[0];
    const float* emb = (const float*)d_in[1];
    float* out = (float*)d_out;

    cudaFuncSetAttribute(k_main, cudaFuncAttributeMaxDynamicSharedMemorySize, 229376);

    k_prep<<<dim3(32, 8), dim3(32, 8)>>>(emb);
    k_ee<<<4, 256>>>(emb);
    k_main<<<NCTA, 256, 229376>>>(lat, emb, out);
    k_red<<<32, 256>>>();
    k_fin<<<1, 1024>>>(out);
}

// round 3
// speedup vs baseline: 1.0005x; 1.0005x over previous
#include <cuda_runtime.h>
#include <math.h>

// ---------------------------------------------------------------------------
// VectorQuantizerLinearSoft: fused fp32 implementation
//   latents [65536, 256] fp32, embedding [1024, 256] fp32
// Outputs (flattened fp32, reference return order):
//   quantized[B*D], vq_loss, entropy, hard_idx[B], hard_quant[B*D],
//   probs[B*K], cluster_metric
// ---------------------------------------------------------------------------

constexpr int NB = 65536;
constexpr int ND = 256;
constexpr int NK = 1024;
constexpr int BM = 32;               // rows per CTA
constexpr int NCTA = NB / BM;        // 2048

constexpr size_t OFF_Q   = 0;
constexpr size_t OFF_VQ  = 16777216;
constexpr size_t OFF_ENT = 16777217;
constexpr size_t OFF_IDX = 16777218;
constexpr size_t OFF_HQ  = 16842754;   // float-offset % 4 == 2  -> only 8B aligned!
constexpr size_t OFF_P   = 33619970;
constexpr size_t OFF_CM  = 100728834;

// Scratch (device globals: no allocations allowed)
__device__ float g_eT[ND * NK];          // embedding transposed [d][c], 1MB
__device__ float g_ee[NK];               // ||e_j||^2
__device__ float g_pavg[NCTA * NK];      // per-CTA column sums of probs (8MB)
__device__ float g_pavg2[32 * NK];       // stage-2 partials
__device__ float g_ploss[NCTA];          // per-CTA sum of (q-z)^2
__device__ float g_pmind[NCTA];          // per-CTA sum of min dist

// ---------------- cp.async helpers ----------------
__device__ __forceinline__ void cp16(void* smem, const void* gmem) {
    unsigned s = (unsigned)__cvta_generic_to_shared(smem);
    asm volatile("cp.async.cg.shared.global [%0], [%1], 16;\n" :: "r"(s), "l"(gmem));
}
__device__ __forceinline__ void cp_commit() { asm volatile("cp.async.commit_group;\n"); }
__device__ __forceinline__ void cp_wait1()  { asm volatile("cp.async.wait_group 1;\n"); }
__device__ __forceinline__ void cp_wait0()  { asm volatile("cp.async.wait_group 0;\n"); }

// ---------------- prep: transpose embedding -> g_eT ----------------
__global__ void k_prep(const float* __restrict__ emb) {
    __shared__ float t[32][33];
    int c0 = blockIdx.x * 32, d0 = blockIdx.y * 32;
    int x = threadIdx.x, y = threadIdx.y;
#pragma unroll
    for (int i = 0; i < 4; ++i) {
        int c = c0 + y + 8 * i;
        t[y + 8 * i][x] = emb[(size_t)c * ND + d0 + x];
    }
    __syncthreads();
#pragma unroll
    for (int i = 0; i < 4; ++i) {
        int d = d0 + y + 8 * i;
        g_eT[(size_t)d * NK + c0 + x] = t[x][y + 8 * i];
    }
}

// ---------------- prep: embedding row norms ----------------
__global__ void k_ee(const float* __restrict__ emb) {
    int warp = (blockIdx.x * blockDim.x + threadIdx.x) >> 5;  // 0..31
    int lane = threadIdx.x & 31;
    for (int rr = 0; rr < 32; ++rr) {
        int row = warp * 32 + rr;
        float s = 0.f;
#pragma unroll
        for (int k = 0; k < 8; ++k) {
            float v = emb[(size_t)row * ND + lane + 32 * k];
            s = fmaf(v, v, s);
        }
#pragma unroll
        for (int off = 16; off; off >>= 1) s += __shfl_xor_sync(0xffffffffu, s, off);
        if (lane == 0) g_ee[row] = s;
    }
}

// ---------------- main fused kernel ----------------
// smem layout (floats):
//   [0, 32768)      GEMM1 eT double buffer (2 x 16x1024)  -> later probs P[32][1024]
//   [32768, 40960)  z tile [32][256]
//   [40960, 57344)  warp colsums [8][1024] -> later GEMM2 e double buffer (2 x 32x256)
__global__ void __launch_bounds__(256, 1)
k_main(const float* __restrict__ lat, const float* __restrict__ emb,
       float* __restrict__ out) {
    extern __shared__ float sm[];
    float* sP  = sm;
    float* sZ  = sm + 32768;
    float* sX  = sm + 40960;   // colsum / GEMM2 buffers

    __shared__ float s_zz[BM];
    __shared__ float s_mind[BM];
    __shared__ int   s_idx[BM];
    __shared__ float s_red[8];

    const int cta  = blockIdx.x;
    const int row0 = cta * BM;
    const int tid  = threadIdx.x;
    const int w    = tid >> 5;
    const int lane = tid & 31;

    // ---- prefetch GEMM1 chunk 0 (eT rows 0..15, 64KB) ----
    {
        const float* src = g_eT;
        float* dst = sm;  // buffer 0
        for (int i = tid; i < 4096; i += 256) cp16(dst + i * 4, src + i * 4);
        cp_commit();
    }

    // ---- load z tile ----
    for (int i = tid; i < BM * ND / 4; i += 256)
        ((float4*)sZ)[i] = ((const float4*)(lat + (size_t)row0 * ND))[i];
    __syncthreads();

    // ---- zz per row ----
#pragma unroll
    for (int i = 0; i < 4; ++i) {
        int r = w * 4 + i;
        float s = 0.f;
#pragma unroll
        for (int k = 0; k < 8; ++k) {
            float v = sZ[r * ND + lane + 32 * k];
            s = fmaf(v, v, s);
        }
#pragma unroll
        for (int off = 16; off; off >>= 1) s += __shfl_xor_sync(0xffffffffu, s, off);
        if (lane == 0) s_zz[r] = s;
    }

    // ---- GEMM1: acc[i][j] = z[4w+i] . e[lane+32j] ----
    float acc[4][32];
#pragma unroll
    for (int i = 0; i < 4; ++i)
#pragma unroll
        for (int j = 0; j < 32; ++j) acc[i][j] = 0.f;

#pragma unroll 1
    for (int ch = 0; ch < 16; ++ch) {
        if (ch < 15) {
            const float* src = g_eT + (size_t)(ch + 1) * 16 * NK;
            float* dst = sm + ((ch + 1) & 1) * 16384;
            for (int i = tid; i < 4096; i += 256) cp16(dst + i * 4, src + i * 4);
            cp_commit();
            cp_wait1();
        } else {
            cp_wait0();
        }
        __syncthreads();

        const float* bufp = sm + (ch & 1) * 16384;
        const float* zrow = sZ + (w * 4) * ND + ch * 16;
#pragma unroll 4
        for (int kk = 0; kk < 16; ++kk) {
            float z0 = zrow[kk];
            float z1 = zrow[256 + kk];
            float z2 = zrow[512 + kk];
            float z3 = zrow[768 + kk];
            const float* er = bufp + kk * NK + lane;
#pragma unroll
            for (int j = 0; j < 32; ++j) {
                float ev = er[j * 32];
                acc[0][j] = fmaf(z0, ev, acc[0][j]);
                acc[1][j] = fmaf(z1, ev, acc[1][j]);
                acc[2][j] = fmaf(z2, ev, acc[2][j]);
                acc[3][j] = fmaf(z3, ev, acc[3][j]);
            }
        }
        __syncthreads();
    }

    // ---- dist, argmin, softmax; write probs to smem + gmem ----
    // Replicate reference elementwise ops exactly: t = zz + ee; dist = t - 2*g
#pragma unroll
    for (int i = 0; i < 4; ++i) {
        int r = w * 4 + i;
        float zz = s_zz[r];
        float dmin = 3.4e38f;
        int imin = NK;
#pragma unroll
        for (int j = 0; j < 32; ++j) {
            float ee = __ldg(&g_ee[lane + 32 * j]);
            float di = __fsub_rn(__fadd_rn(zz, ee), __fmul_rn(2.0f, acc[i][j]));
            acc[i][j] = di;
            int col = lane + 32 * j;
            if (di < dmin) { dmin = di; imin = col; }   // cols ascending -> first min
        }
#pragma unroll
        for (int off = 16; off; off >>= 1) {
            float od = __shfl_xor_sync(0xffffffffu, dmin, off);
            int   oi = __shfl_xor_sync(0xffffffffu, imin, off);
            if (od < dmin || (od == dmin && oi < imin)) { dmin = od; imin = oi; }
        }
        if (lane == 0) { s_mind[r] = dmin; s_idx[r] = imin; }

        float ssum = 0.f;
#pragma unroll
        for (int j = 0; j < 32; ++j) {
            float pv = __expf(-10.0f * (acc[i][j] - dmin));
            acc[i][j] = pv;
            ssum += pv;
        }
#pragma unroll
        for (int off = 16; off; off >>= 1) ssum += __shfl_xor_sync(0xffffffffu, ssum, off);
        float rinv = 1.0f / ssum;
        float* pout = out + OFF_P + (size_t)(row0 + r) * NK;
#pragma unroll
        for (int j = 0; j < 32; ++j) {
            float p = acc[i][j] * rinv;
            acc[i][j] = p;
            sP[r * NK + lane + 32 * j] = p;
            pout[lane + 32 * j] = p;
        }
    }

    // ---- per-warp column sums (for avg_probs) ----
#pragma unroll
    for (int j = 0; j < 32; ++j) {
        float cs = acc[0][j] + acc[1][j] + acc[2][j] + acc[3][j];
        sX[w * NK + lane + 32 * j] = cs;
    }
    __syncthreads();

    for (int c = tid; c < NK; c += 256) {
        float s = 0.f;
#pragma unroll
        for (int ww = 0; ww < 8; ++ww) s += sX[ww * NK + c];
        g_pavg[(size_t)cta * NK + c] = s;
    }

    // min-dist partial + hard index output
    if (tid == 0) {
        float s = 0.f;
        for (int r = 0; r < BM; ++r) s += s_mind[r];
        g_pmind[cta] = s;
    }
    if (tid < BM) out[OFF_IDX + row0 + tid] = (float)s_idx[tid];

    // hard quantized = embedding[idx]  -- float2: OFF_HQ is only 8B-aligned
    for (int i = tid; i < BM * ND / 2; i += 256) {
        int r = i >> 7, d2 = i & 127;
        float2 v = ((const float2*)(emb + (size_t)s_idx[r] * ND))[d2];
        ((float2*)(out + OFF_HQ + (size_t)row0 * ND))[i] = v;
    }
    __syncthreads();  // sX (colsums) consumed before GEMM2 buffers reuse it

    // ---- GEMM2: q = P @ emb ----
    float qacc[4][8];
#pragma unroll
    for (int i = 0; i < 4; ++i)
#pragma unroll
        for (int m = 0; m < 8; ++m) qacc[i][m] = 0.f;

    {   // prefetch chunk 0 (emb rows 0..31, 32KB)
        const float* src = emb;
        float* dst = sX;
        for (int i = tid; i < 2048; i += 256) cp16(dst + i * 4, src + i * 4);
        cp_commit();
    }

#pragma unroll 1
    for (int ch = 0; ch < 32; ++ch) {
        if (ch < 31) {
            const float* src = emb + (size_t)(ch + 1) * 32 * ND;
            float* dst = sX + ((ch + 1) & 1) * 8192;
            for (int i = tid; i < 2048; i += 256) cp16(dst + i * 4, src + i * 4);
            cp_commit();
            cp_wait1();
        } else {
            cp_wait0();
        }
        __syncthreads();

        const float* bp   = sX + (ch & 1) * 8192;
        const float* prow = sP + (w * 4) * NK + ch * 32;
#pragma unroll 4
        for (int c = 0; c < 32; ++c) {
            float p0 = prow[c];
            float p1 = prow[NK + c];
            float p2 = prow[2 * NK + c];
            float p3 = prow[3 * NK + c];
            const float* er = bp + c * ND + lane;
#pragma unroll
            for (int m = 0; m < 8; ++m) {
                float ev = er[32 * m];
                qacc[0][m] = fmaf(p0, ev, qacc[0][m]);
                qacc[1][m] = fmaf(p1, ev, qacc[1][m]);
                qacc[2][m] = fmaf(p2, ev, qacc[2][m]);
                qacc[3][m] = fmaf(p3, ev, qacc[3][m]);
            }
        }
        __syncthreads();
    }

    // ---- write q, accumulate loss ----
    float lp = 0.f;
#pragma unroll
    for (int i = 0; i < 4; ++i) {
        int r = w * 4 + i;
        float* qout = out + OFF_Q + (size_t)(row0 + r) * ND;
#pragma unroll
        for (int m = 0; m < 8; ++m) {
            int d = lane + 32 * m;
            float qv = qacc[i][m];
            qout[d] = qv;
            float dz = qv - sZ[r * ND + d];
            lp = fmaf(dz, dz, lp);
        }
    }
#pragma unroll
    for (int off = 16; off; off >>= 1) lp += __shfl_xor_sync(0xffffffffu, lp, off);
    if (lane == 0) s_red[w] = lp;
    __syncthreads();
    if (tid == 0) {
        float s = 0.f;
        for (int ww = 0; ww < 8; ++ww) s += s_red[ww];
        g_ploss[cta] = s;
    }
}

// ---------------- stage-2 avg_probs reduction ----------------
__global__ void k_red() {
    int g = blockIdx.x;  // 0..31
    for (int c = threadIdx.x; c < NK; c += 256) {
        float s = 0.f;
        for (int r = 0; r < 64; ++r) s += g_pavg[(size_t)(g * 64 + r) * NK + c];
        g_pavg2[g * NK + c] = s;
    }
}

// ---------------- finalize scalars ----------------
__global__ void k_fin(float* __restrict__ out) {
    __shared__ float red[1024];
    int t = threadIdx.x;

    // entropy
    float a = 0.f;
    for (int gg = 0; gg < 32; ++gg) a += g_pavg2[gg * NK + t];
    a *= (1.0f / 65536.0f);
    red[t] = -a * logf(a + 1e-10f);
    __syncthreads();
    for (int s = 512; s; s >>= 1) { if (t < s) red[t] += red[t + s]; __syncthreads(); }
    float ent = red[0];
    __syncthreads();

    // vq loss
    red[t] = g_ploss[t] + g_ploss[t + 1024];
    __syncthreads();
    for (int s = 512; s; s >>= 1) { if (t < s) red[t] += red[t + s]; __syncthreads(); }
    float mse = red[0] * (1.0f / 16777216.0f);
    float vq  = __fadd_rn(__fmul_rn(mse, 0.25f), mse);
    __syncthreads();

    // cluster metric
    red[t] = g_pmind[t] + g_pmind[t + 1024];
    __syncthreads();
    for (int s = 512; s; s >>= 1) { if (t < s) red[t] += red[t + s]; __syncthreads(); }
    float cm = red[0] * (1.0f / 65536.0f);

    if (t == 0) {
        out[OFF_VQ]  = vq;
        out[OFF_ENT] = ent;
        out[OFF_CM]  = cm;
    }
}

// ---------------- launch ----------------
extern "C" void kernel_launch(void* const* d_in, const int* in_sizes, int n_in,
                              void* d_out, int out_size) {
    const float* lat = (const float*)d_in[0];
    const float* emb = (const float*)d_in[1];
    float* out = (float*)d_out;

    cudaFuncSetAttribute(k_main, cudaFuncAttributeMaxDynamicSharedMemorySize, 229376);

    k_prep<<<dim3(32, 8), dim3(32, 8)>>>(emb);
    k_ee<<<4, 256>>>(emb);
    k_main<<<NCTA, 256, 229376>>>(lat, emb, out);
    k_red<<<32, 256>>>();
    k_fin<<<1, 1024>>>(out);
}

// round 4
// speedup vs baseline: 1.0009x; 1.0004x over previous
#include <cuda_runtime.h>
#include <math.h>

// ---------------------------------------------------------------------------
// VectorQuantizerLinearSoft: fused fp32 implementation
//   latents [65536, 256] fp32, embedding [1024, 256] fp32
// Outputs (flattened fp32, reference return order):
//   quantized[B*D], vq_loss, entropy, hard_idx[B], hard_quant[B*D],
//   probs[B*K], cluster_metric
// ---------------------------------------------------------------------------

constexpr int NB = 65536;
constexpr int ND = 256;
constexpr int NK = 1024;
constexpr int BM = 32;               // rows per CTA
constexpr int NCTA = NB / BM;        // 2048

constexpr size_t OFF_Q   = 0;
constexpr size_t OFF_VQ  = 16777216;
constexpr size_t OFF_ENT = 16777217;
constexpr size_t OFF_IDX = 16777218;
constexpr size_t OFF_HQ  = 16842754;   // float-offset % 4 == 2  -> only 8B aligned!
constexpr size_t OFF_P   = 33619970;
constexpr size_t OFF_CM  = 100728834;

// Scratch (device globals: no allocations allowed)
__device__ float g_eT[ND * NK];          // embedding transposed [d][c], 1MB
__device__ float g_ee[NK];               // ||e_j||^2
__device__ float g_pavg[NCTA * NK];      // per-CTA column sums of probs (8MB)
__device__ float g_pavg2[32 * NK];       // stage-2 partials
__device__ float g_ploss[NCTA];          // per-CTA sum of (q-z)^2
__device__ float g_pmind[NCTA];          // per-CTA sum of min dist

// ---------------- cp.async helpers ----------------
__device__ __forceinline__ void cp16(void* smem, const void* gmem) {
    unsigned s = (unsigned)__cvta_generic_to_shared(smem);
    asm volatile("cp.async.cg.shared.global [%0], [%1], 16;\n" :: "r"(s), "l"(gmem));
}
__device__ __forceinline__ void cp_commit() { asm volatile("cp.async.commit_group;\n"); }
__device__ __forceinline__ void cp_wait1()  { asm volatile("cp.async.wait_group 1;\n"); }
__device__ __forceinline__ void cp_wait0()  { asm volatile("cp.async.wait_group 0;\n"); }

// ---------------- prep: transpose embedding -> g_eT ----------------
__global__ void k_prep(const float* __restrict__ emb) {
    __shared__ float t[32][33];
    int c0 = blockIdx.x * 32, d0 = blockIdx.y * 32;
    int x = threadIdx.x, y = threadIdx.y;
#pragma unroll
    for (int i = 0; i < 4; ++i) {
        int c = c0 + y + 8 * i;
        t[y + 8 * i][x] = emb[(size_t)c * ND + d0 + x];
    }
    __syncthreads();
#pragma unroll
    for (int i = 0; i < 4; ++i) {
        int d = d0 + y + 8 * i;
        g_eT[(size_t)d * NK + c0 + x] = t[x][y + 8 * i];
    }
}

// ---------------- prep: embedding row norms ----------------
__global__ void k_ee(const float* __restrict__ emb) {
    int warp = (blockIdx.x * blockDim.x + threadIdx.x) >> 5;  // 0..31
    int lane = threadIdx.x & 31;
    for (int rr = 0; rr < 32; ++rr) {
        int row = warp * 32 + rr;
        float s = 0.f;
#pragma unroll
        for (int k = 0; k < 8; ++k) {
            float v = emb[(size_t)row * ND + lane + 32 * k];
            s = fmaf(v, v, s);
        }
#pragma unroll
        for (int off = 16; off; off >>= 1) s += __shfl_xor_sync(0xffffffffu, s, off);
        if (lane == 0) g_ee[row] = s;
    }
}

// ---------------- main fused kernel ----------------
// smem layout (floats):
//   [0, 32768)      GEMM1 eT double buffer (2 x 16x1024)  -> later probs P[32][1024]
//   [32768, 40960)  z tile [32][256]
//   [40960, 57344)  warp colsums [8][1024] -> later GEMM2 e double buffer (2 x 32x256)
__global__ void __launch_bounds__(256, 1)
k_main(const float* __restrict__ lat, const float* __restrict__ emb,
       float* __restrict__ out) {
    extern __shared__ float sm[];
    float* sP  = sm;
    float* sZ  = sm + 32768;
    float* sX  = sm + 40960;   // colsum / GEMM2 buffers

    __shared__ float s_zz[BM];
    __shared__ float s_mind[BM];
    __shared__ int   s_idx[BM];
    __shared__ float s_red[8];

    const int cta  = blockIdx.x;
    const int row0 = cta * BM;
    const int tid  = threadIdx.x;
    const int w    = tid >> 5;
    const int lane = tid & 31;

    // ---- prefetch GEMM1 chunk 0 (eT rows 0..15, 64KB) ----
    {
        const float* src = g_eT;
        float* dst = sm;  // buffer 0
        for (int i = tid; i < 4096; i += 256) cp16(dst + i * 4, src + i * 4);
        cp_commit();
    }

    // ---- load z tile ----
    for (int i = tid; i < BM * ND / 4; i += 256)
        ((float4*)sZ)[i] = ((const float4*)(lat + (size_t)row0 * ND))[i];
    __syncthreads();

    // ---- zz per row ----
#pragma unroll
    for (int i = 0; i < 4; ++i) {
        int r = w * 4 + i;
        float s = 0.f;
#pragma unroll
        for (int k = 0; k < 8; ++k) {
            float v = sZ[r * ND + lane + 32 * k];
            s = fmaf(v, v, s);
        }
#pragma unroll
        for (int off = 16; off; off >>= 1) s += __shfl_xor_sync(0xffffffffu, s, off);
        if (lane == 0) s_zz[r] = s;
    }

    // ---- GEMM1: acc[i][j] = z[4w+i] . e[lane+32j] ----
    float acc[4][32];
#pragma unroll
    for (int i = 0; i < 4; ++i)
#pragma unroll
        for (int j = 0; j < 32; ++j) acc[i][j] = 0.f;

#pragma unroll 1
    for (int ch = 0; ch < 16; ++ch) {
        if (ch < 15) {
            const float* src = g_eT + (size_t)(ch + 1) * 16 * NK;
            float* dst = sm + ((ch + 1) & 1) * 16384;
            for (int i = tid; i < 4096; i += 256) cp16(dst + i * 4, src + i * 4);
            cp_commit();
            cp_wait1();
        } else {
            cp_wait0();
        }
        __syncthreads();

        const float* bufp = sm + (ch & 1) * 16384;
        const float* zrow = sZ + (w * 4) * ND + ch * 16;
#pragma unroll 4
        for (int kk = 0; kk < 16; ++kk) {
            float z0 = zrow[kk];
            float z1 = zrow[256 + kk];
            float z2 = zrow[512 + kk];
            float z3 = zrow[768 + kk];
            const float* er = bufp + kk * NK + lane;
#pragma unroll
            for (int j = 0; j < 32; ++j) {
                float ev = er[j * 32];
                acc[0][j] = fmaf(z0, ev, acc[0][j]);
                acc[1][j] = fmaf(z1, ev, acc[1][j]);
                acc[2][j] = fmaf(z2, ev, acc[2][j]);
                acc[3][j] = fmaf(z3, ev, acc[3][j]);
            }
        }
        __syncthreads();
    }

    // ---- dist, argmin, softmax; write probs to smem + gmem ----
    // Replicate reference elementwise ops exactly: t = zz + ee; dist = t - 2*g
#pragma unroll
    for (int i = 0; i < 4; ++i) {
        int r = w * 4 + i;
        float zz = s_zz[r];
        float dmin = 3.4e38f;
        int imin = NK;
#pragma unroll
        for (int j = 0; j < 32; ++j) {
            float ee = __ldg(&g_ee[lane + 32 * j]);
            float di = __fsub_rn(__fadd_rn(zz, ee), __fmul_rn(2.0f, acc[i][j]));
            acc[i][j] = di;
            int col = lane + 32 * j;
            if (di < dmin) { dmin = di; imin = col; }   // cols ascending -> first min
        }
#pragma unroll
        for (int off = 16; off; off >>= 1) {
            float od = __shfl_xor_sync(0xffffffffu, dmin, off);
            int   oi = __shfl_xor_sync(0xffffffffu, imin, off);
            if (od < dmin || (od == dmin && oi < imin)) { dmin = od; imin = oi; }
        }
        if (lane == 0) { s_mind[r] = dmin; s_idx[r] = imin; }

        float ssum = 0.f;
#pragma unroll
        for (int j = 0; j < 32; ++j) {
            float pv = __expf(-10.0f * (acc[i][j] - dmin));
            acc[i][j] = pv;
            ssum += pv;
        }
#pragma unroll
        for (int off = 16; off; off >>= 1) ssum += __shfl_xor_sync(0xffffffffu, ssum, off);
        float rinv = 1.0f / ssum;
        float* pout = out + OFF_P + (size_t)(row0 + r) * NK;
#pragma unroll
        for (int j = 0; j < 32; ++j) {
            float p = acc[i][j] * rinv;
            acc[i][j] = p;
            sP[r * NK + lane + 32 * j] = p;
            pout[lane + 32 * j] = p;
        }
    }

    // ---- per-warp column sums (for avg_probs) ----
#pragma unroll
    for (int j = 0; j < 32; ++j) {
        float cs = acc[0][j] + acc[1][j] + acc[2][j] + acc[3][j];
        sX[w * NK + lane + 32 * j] = cs;
    }
    __syncthreads();

    for (int c = tid; c < NK; c += 256) {
        float s = 0.f;
#pragma unroll
        for (int ww = 0; ww < 8; ++ww) s += sX[ww * NK + c];
        g_pavg[(size_t)cta * NK + c] = s;
    }

    // min-dist partial + hard index output
    if (tid == 0) {
        float s = 0.f;
        for (int r = 0; r < BM; ++r) s += s_mind[r];
        g_pmind[cta] = s;
    }
    if (tid < BM) out[OFF_IDX + row0 + tid] = (float)s_idx[tid];

    // hard quantized = embedding[idx]  -- float2: OFF_HQ is only 8B-aligned
    for (int i = tid; i < BM * ND / 2; i += 256) {
        int r = i >> 7, d2 = i & 127;
        float2 v = ((const float2*)(emb + (size_t)s_idx[r] * ND))[d2];
        ((float2*)(out + OFF_HQ + (size_t)row0 * ND))[i] = v;
    }
    __syncthreads();  // sX (colsums) consumed before GEMM2 buffers reuse it

    // ---- GEMM2: q = P @ emb ----
    float qacc[4][8];
#pragma unroll
    for (int i = 0; i < 4; ++i)
#pragma unroll
        for (int m = 0; m < 8; ++m) qacc[i][m] = 0.f;

    {   // prefetch chunk 0 (emb rows 0..31, 32KB)
        const float* src = emb;
        float* dst = sX;
        for (int i = tid; i < 2048; i += 256) cp16(dst + i * 4, src + i * 4);
        cp_commit();
    }

#pragma unroll 1
    for (int ch = 0; ch < 32; ++ch) {
        if (ch < 31) {
            const float* src = emb + (size_t)(ch + 1) * 32 * ND;
            float* dst = sX + ((ch + 1) & 1) * 8192;
            for (int i = tid; i < 2048; i += 256) cp16(dst + i * 4, src + i * 4);
            cp_commit();
            cp_wait1();
        } else {
            cp_wait0();
        }
        __syncthreads();

        const float* bp   = sX + (ch & 1) * 8192;
        const float* prow = sP + (w * 4) * NK + ch * 32;
#pragma unroll 4
        for (int c = 0; c < 32; ++c) {
            float p0 = prow[c];
            float p1 = prow[NK + c];
            float p2 = prow[2 * NK + c];
            float p3 = prow[3 * NK + c];
            const float* er = bp + c * ND + lane;
#pragma unroll
            for (int m = 0; m < 8; ++m) {
                float ev = er[32 * m];
                qacc[0][m] = fmaf(p0, ev, qacc[0][m]);
                qacc[1][m] = fmaf(p1, ev, qacc[1][m]);
                qacc[2][m] = fmaf(p2, ev, qacc[2][m]);
                qacc[3][m] = fmaf(p3, ev, qacc[3][m]);
            }
        }
        __syncthreads();
    }

    // ---- write q, accumulate loss ----
    float lp = 0.f;
#pragma unroll
    for (int i = 0; i < 4; ++i) {
        int r = w * 4 + i;
        float* qout = out + OFF_Q + (size_t)(row0 + r) * ND;
#pragma unroll
        for (int m = 0; m < 8; ++m) {
            int d = lane + 32 * m;
            float qv = qacc[i][m];
            qout[d] = qv;
            float dz = qv - sZ[r * ND + d];
            lp = fmaf(dz, dz, lp);
        }
    }
#pragma unroll
    for (int off = 16; off; off >>= 1) lp += __shfl_xor_sync(0xffffffffu, lp, off);
    if (lane == 0) s_red[w] = lp;
    __syncthreads();
    if (tid == 0) {
        float s = 0.f;
        for (int ww = 0; ww < 8; ++ww) s += s_red[ww];
        g_ploss[cta] = s;
    }
}

// ---------------- stage-2 avg_probs reduction ----------------
__global__ void k_red() {
    int g = blockIdx.x;  // 0..31
    for (int c = threadIdx.x; c < NK; c += 256) {
        float s = 0.f;
        for (int r = 0; r < 64; ++r) s += g_pavg[(size_t)(g * 64 + r) * NK + c];
        g_pavg2[g * NK + c] = s;
    }
}

// ---------------- finalize scalars ----------------
__global__ void k_fin(float* __restrict__ out) {
    __shared__ float red[1024];
    int t = threadIdx.x;

    // entropy
    float a = 0.f;
    for (int gg = 0; gg < 32; ++gg) a += g_pavg2[gg * NK + t];
    a *= (1.0f / 65536.0f);
    red[t] = -a * logf(a + 1e-10f);
    __syncthreads();
    for (int s = 512; s; s >>= 1) { if (t < s) red[t] += red[t + s]; __syncthreads(); }
    float ent = red[0];
    __syncthreads();

    // vq loss
    red[t] = g_ploss[t] + g_ploss[t + 1024];
    __syncthreads();
    for (int s = 512; s; s >>= 1) { if (t < s) red[t] += red[t + s]; __syncthreads(); }
    float mse = red[0] * (1.0f / 16777216.0f);
    float vq  = __fadd_rn(__fmul_rn(mse, 0.25f), mse);
    __syncthreads();

    // cluster metric
    red[t] = g_pmind[t] + g_pmind[t + 1024];
    __syncthreads();
    for (int s = 512; s; s >>= 1) { if (t < s) red[t] += red[t + s]; __syncthreads(); }
    float cm = red[0] * (1.0f / 65536.0f);

    if (t == 0) {
        out[OFF_VQ]  = vq;
        out[OFF_ENT] = ent;
        out[OFF_CM]  = cm;
    }
}

// ---------------- launch ----------------
extern "C" void kernel_launch(void* const* d_in, const int* in_sizes, int n_in,
                              void* d_out, int out_size) {
    const float* lat = (const float*)d_in[0];
    const float* emb = (const float*)d_in[1];
    float* out = (float*)d_out;

    cudaFuncSetAttribute(k_main, cudaFuncAttributeMaxDynamicSharedMemorySize, 229376);

    k_prep<<<dim3(32, 8), dim3(32, 8)>>>(emb);
    k_ee<<<4, 256>>>(emb);
    k_main<<<NCTA, 256, 229376>>>(lat, emb, out);
    k_red<<<32, 256>>>();
    k_fin<<<1, 1024>>>(out);
}

// round 7
// speedup vs baseline: 1.6243x; 1.6228x over previous
#include <cuda_runtime.h>
#include <math.h>
#include <stdint.h>

// ---------------------------------------------------------------------------
// VectorQuantizerLinearSoft — tcgen05 3xTF32 GEMMs + exact-FFMA argmin refine
//   Accelerated device pass (sm_103a/sm_100a): tcgen05 tensor GEMMs
//   Family/base pass (compute_103): FFMA fallback (proven R4 structure)
// ---------------------------------------------------------------------------

#if defined(__CUDA_ARCH_FEAT_SM103_ALL) || defined(__CUDA_ARCH_FEAT_SM100_ALL)
#define HAS_TC 1
#else
#define HAS_TC 0
#endif

constexpr int NB = 65536;
constexpr int ND = 256;
constexpr int NK = 1024;

constexpr size_t OFF_Q   = 0;
constexpr size_t OFF_VQ  = 16777216;
constexpr size_t OFF_ENT = 16777217;
constexpr size_t OFF_IDX = 16777218;
constexpr size_t OFF_HQ  = 16842754;   // only 8B-aligned
constexpr size_t OFF_P   = 33619970;   // only 8B-aligned
constexpr size_t OFF_CM  = 100728834;

// Scratch (device globals: no allocations allowed)
__device__ float g_G[(size_t)NB * NK];     // 256MB  lat @ emb^T
__device__ float g_eT[ND * NK];            // emb^T full precision (fallback GEMM1)
__device__ float g_emb2[NK * 768];         // emb thirds [hi | hi | lo], rows j
__device__ float g_embT2[ND * 3072];       // emb^T thirds [hi | hi | lo], rows d
__device__ float g_ee[NK];                 // ||e_j||^2
__device__ float g_pavg[2048 * NK];        // per-soft-CTA colsums of probs
__device__ float g_pavg2[32 * NK];
__device__ float g_ploss[512];             // per-GEMM2-CTA sum (q-z)^2
__device__ float g_pmind[2048];            // per-soft-CTA sum min dist

// ---------------- generic helpers ----------------
__device__ __forceinline__ void cp16(void* smem, const void* gmem) {
    unsigned s = (unsigned)__cvta_generic_to_shared(smem);
    asm volatile("cp.async.cg.shared.global [%0], [%1], 16;\n" :: "r"(s), "l"(gmem));
}
__device__ __forceinline__ void cp_commit() { asm volatile("cp.async.commit_group;\n"); }
__device__ __forceinline__ void cp_wait1()  { asm volatile("cp.async.wait_group 1;\n"); }
__device__ __forceinline__ void cp_wait0()  { asm volatile("cp.async.wait_group 0;\n"); }

__device__ __forceinline__ float tf32hi(float x) {
    uint32_t u; asm("cvt.rna.tf32.f32 %0, %1;" : "=r"(u) : "f"(x));
    return __uint_as_float(u);
}
// third 0/2 -> hi part, third 1 -> lo part
__device__ __forceinline__ float splitv(float x, int third) {
    float h = tf32hi(x);
    return (third == 1) ? __fsub_rn(x, h) : h;
}
__device__ __forceinline__ uint32_t sw128(uint32_t off) { return off ^ ((off >> 3) & 0x70); }

// ---------------- tcgen05 helpers (accelerated pass only) ----------------
#if HAS_TC
__device__ __forceinline__ uint32_t smem_u32(const void* p) {
    uint32_t a;
    asm("{ .reg .u64 t; cvta.to.shared.u64 t, %1; cvt.u32.u64 %0, t; }" : "=r"(a) : "l"(p));
    return a;
}
__device__ __forceinline__ uint32_t elect1() {
    uint32_t p;
    asm volatile("{ .reg .pred p; elect.sync _|p, 0xFFFFFFFF; selp.b32 %0, 1, 0, p; }" : "=r"(p));
    return p;
}
// SW128 K-major smem descriptor (SBO=64, LBO=1, layout SW128, Blackwell v1)
__device__ __forceinline__ uint64_t sdesc(uint32_t addr) {
    return 0x4000404000010000ULL | ((uint64_t)(addr >> 4) & 0x3FFF);
}
// idesc: dtype=F32, atype=btype=TF32(2), N=256, M=128, K-major both
constexpr uint32_t IDESC_TF32_N256 =
    (1u << 4) | (2u << 7) | (2u << 10) | ((256u / 8) << 17) | ((128u / 16) << 24);

__device__ __forceinline__ void mma_tf32(uint32_t d, uint64_t ad, uint64_t bd,
                                         uint32_t idesc, bool en) {
    uint32_t e = en ? 1u : 0u;
    asm volatile(
        "{\n\t.reg .pred p;\n\tsetp.ne.u32 p, %5, 0;\n\t"
        "tcgen05.mma.cta_group::1.kind::tf32 [%0], %1, %2, %3, {%4, %4, %4, %4}, p;\n\t}"
        :: "r"(d), "l"(ad), "l"(bd), "r"(idesc), "r"(0u), "r"(e) : "memory");
}

#define FENCE_PROXY()     asm volatile("fence.proxy.async.shared::cta;" ::: "memory")
#define TC_ALLOC(sa, n)   asm volatile("tcgen05.alloc.cta_group::1.sync.aligned.shared::cta.b32 [%0], %1;" :: "r"(sa), "r"(n) : "memory")
#define TC_DEALLOC(t, n)  asm volatile("tcgen05.dealloc.cta_group::1.sync.aligned.b32 %0, %1;" :: "r"(t), "r"(n))
#define TC_COMMIT(mb)     asm volatile("tcgen05.commit.cta_group::1.mbarrier::arrive::one.shared::cluster.b64 [%0];" :: "r"(mb) : "memory")
#define TC_WAIT_LD()      asm volatile("tcgen05.wait::ld.sync.aligned;" ::: "memory")
#define TC_FENCE_AFTER()  asm volatile("tcgen05.fence::after_thread_sync;" ::: "memory")
#define TC_FENCE_BEFORE() asm volatile("tcgen05.fence::before_thread_sync;" ::: "memory")
#define MBAR_INIT(mb, c)  asm volatile("mbarrier.init.shared.b64 [%0], %1;" :: "r"(mb), "r"(c) : "memory")
#define MBAR_INVAL(mb)    asm volatile("mbarrier.inval.shared.b64 [%0];" :: "r"(mb) : "memory")

#define MBAR_WAIT(mb, par) do {                                              \
    uint32_t _m = (mb), _p = (par), _d;                                      \
    asm volatile("{\n\t.reg .pred p;\n\t"                                    \
        "mbarrier.try_wait.parity.acquire.cta.shared::cta.b64 p, [%1], %2;\n\t" \
        "selp.b32 %0, 1, 0, p;\n\t}" : "=r"(_d) : "r"(_m), "r"(_p) : "memory"); \
    if (!_d) {                                                               \
        asm volatile("{\n\t.reg .pred P1;\n\t"                               \
            "WL_%=:\n\t"                                                     \
            "mbarrier.try_wait.parity.acquire.cta.shared::cta.b64 P1, [%0], %1, 0x989680;\n\t" \
            "@P1 bra.uni WD_%=;\n\t"                                         \
            "bra.uni WL_%=;\n\t"                                             \
            "WD_%=:\n\t}" :: "r"(_m), "r"(_p) : "memory");                   \
    }                                                                        \
} while (0)

#define LDTM32(r, a)                                                         \
    asm volatile("tcgen05.ld.sync.aligned.32x32b.x32.b32 "                   \
        "{%0,%1,%2,%3,%4,%5,%6,%7,%8,%9,%10,%11,%12,%13,%14,%15,"            \
        "%16,%17,%18,%19,%20,%21,%22,%23,%24,%25,%26,%27,%28,%29,%30,%31}, [%32];" \
        : "=r"((r)[0]), "=r"((r)[1]), "=r"((r)[2]), "=r"((r)[3]),            \
          "=r"((r)[4]), "=r"((r)[5]), "=r"((r)[6]), "=r"((r)[7]),            \
          "=r"((r)[8]), "=r"((r)[9]), "=r"((r)[10]), "=r"((r)[11]),          \
          "=r"((r)[12]), "=r"((r)[13]), "=r"((r)[14]), "=r"((r)[15]),        \
          "=r"((r)[16]), "=r"((r)[17]), "=r"((r)[18]), "=r"((r)[19]),        \
          "=r"((r)[20]), "=r"((r)[21]), "=r"((r)[22]), "=r"((r)[23]),        \
          "=r"((r)[24]), "=r"((r)[25]), "=r"((r)[26]), "=r"((r)[27]),        \
          "=r"((r)[28]), "=r"((r)[29]), "=r"((r)[30]), "=r"((r)[31])         \
        : "r"(a))
#endif  // HAS_TC

// ---------------- prep: emb split tables + transpose + row norms -----------
__global__ void k_prep2(const float* __restrict__ emb) {
    int j = blockIdx.x;  // 0..1023
    for (int c = threadIdx.x; c < 768; c += 256) {
        int cs = c & 255;
        float v = emb[(size_t)j * ND + cs];
        float h = tf32hi(v);
        g_emb2[(size_t)j * 768 + c] = (c < 512) ? h : __fsub_rn(v, h);
    }
    for (int d = threadIdx.x; d < 256; d += 256) {
        float v = emb[(size_t)j * ND + d];
        float h = tf32hi(v);
        g_eT[(size_t)d * NK + j]             = v;
        g_embT2[(size_t)d * 3072 + j]        = h;
        g_embT2[(size_t)d * 3072 + 1024 + j] = h;
        g_embT2[(size_t)d * 3072 + 2048 + j] = __fsub_rn(v, h);
    }
}

__global__ void k_ee(const float* __restrict__ emb) {
    int warp = (blockIdx.x * blockDim.x + threadIdx.x) >> 5;
    int lane = threadIdx.x & 31;
    for (int rr = 0; rr < 32; ++rr) {
        int row = warp * 32 + rr;
        float s = 0.f;
#pragma unroll
        for (int k = 0; k < 8; ++k) {
            float v = emb[(size_t)row * ND + lane + 32 * k];
            s = fmaf(v, v, s);
        }
#pragma unroll
        for (int off = 16; off; off >>= 1) s += __shfl_xor_sync(0xffffffffu, s, off);
        if (lane == 0) g_ee[row] = s;
    }
}

// ---------------- GEMM1: G = lat @ emb^T (M=128/CTA) -----------------------
constexpr int G1_SA0 = 1024, G1_SA1 = 17408, G1_SB0 = 33792, G1_SB1 = 99328;
constexpr int G1_SMEM = 164864;

__global__ void __launch_bounds__(256, 1)
k_gemm1(const float* __restrict__ lat, const float* __restrict__ emb) {
    (void)emb;
#if HAS_TC
    extern __shared__ char smem[];
    uint32_t sbase = smem_u32(smem);
    const int tid = threadIdx.x, wid = tid >> 5;
    const int row0 = blockIdx.x * 128;

    if (wid == 0) TC_ALLOC(sbase, 512);
    if (tid == 0) MBAR_INIT(sbase + 8, 1);
    __syncthreads();
    uint32_t tmem;
    asm volatile("ld.shared.b32 %0, [%1];" : "=r"(tmem) : "r"(sbase));

    const float* latb = lat + (size_t)row0 * ND;

    for (int nt = 0; nt < 2; ++nt) {
        // prefetch chunk 0
        {
            char* ab = smem + G1_SA0;
#pragma unroll
            for (int t = tid; t < 1024; t += 256) {
                int r = t >> 3, c4 = t & 7;
                float4 v = *(const float4*)(latb + (size_t)r * ND + c4 * 4);
                float4 o = make_float4(splitv(v.x, 0), splitv(v.y, 0),
                                       splitv(v.z, 0), splitv(v.w, 0));
                *(float4*)(ab + sw128(r * 128 + c4 * 16)) = o;
            }
            char* bb = smem + G1_SB0;
            const float* bsrc = g_emb2 + (size_t)(nt * 512) * 768;
            for (int t = tid; t < 4096; t += 256) {
                int r = t >> 3, c4 = t & 7;
                cp16(bb + sw128(r * 128 + c4 * 16), bsrc + (size_t)r * 768 + c4 * 4);
            }
            cp_commit();
        }

        for (int kc = 0; kc < 24; ++kc) {
            cp_wait0();
            FENCE_PROXY();
            __syncthreads();
            // safe ordering: wait mma(kc-1) BEFORE issuing commit kc
            if (kc >= 1) { int ci = nt * 24 + kc - 1; MBAR_WAIT(sbase + 8, (uint32_t)(ci & 1)); }
            if (wid == 0) {
                if (elect1()) {
                    uint64_t ad = sdesc(sbase + ((kc & 1) ? G1_SA1 : G1_SA0));
                    uint64_t bd = sdesc(sbase + ((kc & 1) ? G1_SB1 : G1_SB0));
                    bool ch0 = (kc > 0);
#pragma unroll
                    for (int s = 0; s < 4; ++s) {
                        bool en = ch0 || (s > 0);
                        mma_tf32(tmem,       ad + s * 2, bd + s * 2,        IDESC_TF32_N256, en);
                        mma_tf32(tmem + 256, ad + s * 2, bd + 2048 + s * 2, IDESC_TF32_N256, en);
                    }
                    TC_COMMIT(sbase + 8);
                }
            }
            if (kc < 23) {
                int kn = kc + 1;
                char* ab = smem + ((kn & 1) ? G1_SA1 : G1_SA0);
                int third = kn >> 3, cb = (kn & 7) * 32;
#pragma unroll
                for (int t = tid; t < 1024; t += 256) {
                    int r = t >> 3, c4 = t & 7;
                    float4 v = *(const float4*)(latb + (size_t)r * ND + cb + c4 * 4);
                    float4 o = make_float4(splitv(v.x, third), splitv(v.y, third),
                                           splitv(v.z, third), splitv(v.w, third));
                    *(float4*)(ab + sw128(r * 128 + c4 * 16)) = o;
                }
                char* bb = smem + ((kn & 1) ? G1_SB1 : G1_SB0);
                const float* bsrc = g_emb2 + (size_t)(nt * 512) * 768 + kn * 32;
                for (int t = tid; t < 4096; t += 256) {
                    int r = t >> 3, c4 = t & 7;
                    cp16(bb + sw128(r * 128 + c4 * 16), bsrc + (size_t)r * 768 + c4 * 4);
                }
                cp_commit();
            }
        }
        { int ci = nt * 24 + 23; MBAR_WAIT(sbase + 8, (uint32_t)(ci & 1)); }
        TC_FENCE_AFTER();

        // epilogue: D[128 lanes][512 cols] -> G
        {
            int wg = tid >> 7, w4 = (tid >> 5) & 3, lane = tid & 31;
            int row = row0 + w4 * 32 + lane;
#pragma unroll 1
            for (int b = 0; b < 8; ++b) {
                uint32_t r[32];
                LDTM32(r, tmem + wg * 256 + b * 32);
                TC_WAIT_LD();
                float4* gp = (float4*)&g_G[(size_t)row * NK + nt * 512 + wg * 256 + b * 32];
#pragma unroll
                for (int c4 = 0; c4 < 8; ++c4)
                    gp[c4] = make_float4(__uint_as_float(r[c4 * 4 + 0]),
                                         __uint_as_float(r[c4 * 4 + 1]),
                                         __uint_as_float(r[c4 * 4 + 2]),
                                         __uint_as_float(r[c4 * 4 + 3]));
            }
        }
        TC_FENCE_BEFORE();
        __syncthreads();
    }
    if (tid == 0) MBAR_INVAL(sbase + 8);
    __syncthreads();
    if (wid == 0) TC_DEALLOC(tmem, 512);
#else
    // ---------------- FFMA fallback (R4 GEMM1 structure) ----------------
    extern __shared__ float smf[];
    float* sZ = smf;               // 8192 floats
    float* sE = smf + 8192;        // 2 x 16384 floats
    const int tid = threadIdx.x, w = tid >> 5, lane = tid & 31;
    const int row0 = blockIdx.x * 128;

    for (int st = 0; st < 4; ++st) {
        const int r0 = row0 + st * 32;
        for (int i = tid; i < 4096; i += 256) cp16(sE + i * 4, g_eT + i * 4);
        cp_commit();
        for (int i = tid; i < 2048; i += 256)
            ((float4*)sZ)[i] = ((const float4*)(lat + (size_t)r0 * ND))[i];
        __syncthreads();

        float acc[4][32];
#pragma unroll
        for (int i = 0; i < 4; ++i)
#pragma unroll
            for (int j = 0; j < 32; ++j) acc[i][j] = 0.f;

#pragma unroll 1
        for (int ch = 0; ch < 16; ++ch) {
            if (ch < 15) {
                const float* src = g_eT + (size_t)(ch + 1) * 16 * NK;
                float* dst = sE + ((ch + 1) & 1) * 16384;
                for (int i = tid; i < 4096; i += 256) cp16(dst + i * 4, src + i * 4);
                cp_commit();
                cp_wait1();
            } else {
                cp_wait0();
            }
            __syncthreads();

            const float* bufp = sE + (ch & 1) * 16384;
            const float* zrow = sZ + (w * 4) * ND + ch * 16;
#pragma unroll 4
            for (int kk = 0; kk < 16; ++kk) {
                float z0 = zrow[kk];
                float z1 = zrow[256 + kk];
                float z2 = zrow[512 + kk];
                float z3 = zrow[768 + kk];
                const float* er = bufp + kk * NK + lane;
#pragma unroll
                for (int j = 0; j < 32; ++j) {
                    float ev = er[j * 32];
                    acc[0][j] = fmaf(z0, ev, acc[0][j]);
                    acc[1][j] = fmaf(z1, ev, acc[1][j]);
                    acc[2][j] = fmaf(z2, ev, acc[2][j]);
                    acc[3][j] = fmaf(z3, ev, acc[3][j]);
                }
            }
            __syncthreads();
        }
#pragma unroll
        for (int i = 0; i < 4; ++i) {
            float* gp = &g_G[(size_t)(r0 + w * 4 + i) * NK];
#pragma unroll
            for (int j = 0; j < 32; ++j) gp[lane + 32 * j] = acc[i][j];
        }
        __syncthreads();
    }
#endif
}

// ---------------- k_soft: dist/argmin(+exact refine)/softmax + partials ----
__global__ void __launch_bounds__(256)
k_soft(const float* __restrict__ lat, const float* __restrict__ emb,
       float* __restrict__ out) {
    __shared__ float sX[8 * NK];
    __shared__ float s_mind[32];
    __shared__ int   s_idx[32];

    const int cta = blockIdx.x, row0 = cta * 32;
    const int tid = threadIdx.x, w = tid >> 5, lane = tid & 31;

    float acc[4][32];
    float zz[4];
#pragma unroll
    for (int i = 0; i < 4; ++i) {
        int r = row0 + w * 4 + i;
        const float* zr = lat + (size_t)r * ND;
        float s = 0.f;
#pragma unroll
        for (int k = 0; k < 8; ++k) { float v = zr[lane + 32 * k]; s = fmaf(v, v, s); }
#pragma unroll
        for (int off = 16; off; off >>= 1) s += __shfl_xor_sync(0xffffffffu, s, off);
        zz[i] = s;
        const float* gr = g_G + (size_t)r * NK;
#pragma unroll
        for (int j = 0; j < 32; ++j) acc[i][j] = gr[lane + 32 * j];
    }

#pragma unroll
    for (int i = 0; i < 4; ++i) {
        int r = w * 4 + i;
        float dmin = 3.4e38f;
#pragma unroll
        for (int j = 0; j < 32; ++j) {
            float ee = __ldg(&g_ee[lane + 32 * j]);
            float di = __fsub_rn(__fadd_rn(zz[i], ee), __fmul_rn(2.0f, acc[i][j]));
            acc[i][j] = di;
            dmin = fminf(dmin, di);
        }
#pragma unroll
        for (int off = 16; off; off >>= 1)
            dmin = fminf(dmin, __shfl_xor_sync(0xffffffffu, dmin, off));

        // ---- exact-FFMA refinement of argmin ----
        // tensor dist error << 1e-4; every candidate within dmin+1e-4 is
        // re-evaluated with a full-fp32 dot product; ascending-col order
        // gives jnp.argmin first-index tie-break.
        {
            const float* zr = lat + (size_t)(row0 + r) * ND;
            float thr = dmin + 1e-4f;
            float bd = 3.4e38f;
            int   bi = NK;
#pragma unroll 1
            for (int j = 0; j < 32; ++j) {
                unsigned m = __ballot_sync(0xffffffffu, acc[i][j] < thr);
                while (m) {
                    int src = __ffs(m) - 1;
                    m &= m - 1;
                    int col = src + 32 * j;
                    const float* er = emb + (size_t)col * ND;
                    float s = 0.f;
#pragma unroll
                    for (int k = 0; k < 8; ++k)
                        s = fmaf(zr[lane + 32 * k], __ldg(&er[lane + 32 * k]), s);
#pragma unroll
                    for (int off = 16; off; off >>= 1)
                        s += __shfl_xor_sync(0xffffffffu, s, off);
                    float dc = __fsub_rn(__fadd_rn(zz[i], __ldg(&g_ee[col])),
                                         __fmul_rn(2.0f, s));
                    if (dc < bd) { bd = dc; bi = col; }
                }
            }
            if (lane == 0) { s_mind[r] = bd; s_idx[r] = bi; }
        }

        float ssum = 0.f;
#pragma unroll
        for (int j = 0; j < 32; ++j) {
            float pv = __expf(-10.0f * (acc[i][j] - dmin));
            acc[i][j] = pv;
            ssum += pv;
        }
#pragma unroll
        for (int off = 16; off; off >>= 1) ssum += __shfl_xor_sync(0xffffffffu, ssum, off);
        float rinv = 1.0f / ssum;
        float* pout = out + OFF_P + (size_t)(row0 + r) * NK;
#pragma unroll
        for (int j = 0; j < 32; ++j) {
            float p = acc[i][j] * rinv;
            acc[i][j] = p;
            pout[lane + 32 * j] = p;
        }
    }

#pragma unroll
    for (int j = 0; j < 32; ++j)
        sX[w * NK + lane + 32 * j] = acc[0][j] + acc[1][j] + acc[2][j] + acc[3][j];
    __syncthreads();

    for (int c = tid; c < NK; c += 256) {
        float s = 0.f;
#pragma unroll
        for (int ww = 0; ww < 8; ++ww) s += sX[ww * NK + c];
        g_pavg[(size_t)cta * NK + c] = s;
    }
    if (tid == 0) {
        float s = 0.f;
        for (int r = 0; r < 32; ++r) s += s_mind[r];
        g_pmind[cta] = s;
    }
    if (tid < 32) out[OFF_IDX + row0 + tid] = (float)s_idx[tid];

    for (int i = tid; i < 32 * ND / 2; i += 256) {
        int r = i >> 7, d2 = i & 127;
        float2 v = ((const float2*)(emb + (size_t)s_idx[r] * ND))[d2];
        ((float2*)(out + OFF_HQ + (size_t)row0 * ND))[i] = v;
    }
}

// ---------------- GEMM2: Q = P @ emb (M=128/CTA, N=256) --------------------
constexpr int G2_SA0 = 1024, G2_SA1 = 17408, G2_SB0 = 33792, G2_SB1 = 66560;
constexpr int G2_SMEM = 99328;

__global__ void __launch_bounds__(256, 1)
k_gemm2(const float* __restrict__ lat, const float* __restrict__ emb,
        float* __restrict__ out) {
    (void)emb;
#if HAS_TC
    extern __shared__ char smem[];
    uint32_t sbase = smem_u32(smem);
    const int tid = threadIdx.x, wid = tid >> 5;
    const int row0 = blockIdx.x * 128;

    if (wid == 0) TC_ALLOC(sbase, 512);
    if (tid == 0) MBAR_INIT(sbase + 8, 1);
    __syncthreads();
    uint32_t tmem;
    asm volatile("ld.shared.b32 %0, [%1];" : "=r"(tmem) : "r"(sbase));

    const float* pbase = out + OFF_P + (size_t)row0 * NK;

    // prefetch chunk 0
    {
        char* ab = smem + G2_SA0;
#pragma unroll
        for (int t = tid; t < 2048; t += 256) {
            int r = t >> 4, c2 = t & 15;
            float2 v = *(const float2*)(pbase + (size_t)r * NK + c2 * 2);
            float2 o = make_float2(splitv(v.x, 0), splitv(v.y, 0));
            *(float2*)(ab + sw128(r * 128 + c2 * 8)) = o;
        }
        char* bb = smem + G2_SB0;
        for (int t = tid; t < 2048; t += 256) {
            int r = t >> 3, c4 = t & 7;
            cp16(bb + sw128(r * 128 + c4 * 16), g_embT2 + (size_t)r * 3072 + c4 * 4);
        }
        cp_commit();
    }

    for (int kc = 0; kc < 96; ++kc) {
        cp_wait0();
        FENCE_PROXY();
        __syncthreads();
        if (kc >= 1) MBAR_WAIT(sbase + 8, (uint32_t)((kc - 1) & 1));
        if (wid == 0) {
            if (elect1()) {
                uint64_t ad = sdesc(sbase + ((kc & 1) ? G2_SA1 : G2_SA0));
                uint64_t bd = sdesc(sbase + ((kc & 1) ? G2_SB1 : G2_SB0));
#pragma unroll
                for (int s = 0; s < 4; ++s)
                    mma_tf32(tmem, ad + s * 2, bd + s * 2, IDESC_TF32_N256, (kc > 0) || (s > 0));
                TC_COMMIT(sbase + 8);
            }
        }
        if (kc < 95) {
            int kn = kc + 1;
            char* ab = smem + ((kn & 1) ? G2_SA1 : G2_SA0);
            int third = kn >> 5, cb = (kn & 31) * 32;
#pragma unroll
            for (int t = tid; t < 2048; t += 256) {
                int r = t >> 4, c2 = t & 15;
                float2 v = *(const float2*)(pbase + (size_t)r * NK + cb + c2 * 2);
                float2 o = make_float2(splitv(v.x, third), splitv(v.y, third));
                *(float2*)(ab + sw128(r * 128 + c2 * 8)) = o;
            }
            char* bb = smem + ((kn & 1) ? G2_SB1 : G2_SB0);
            const float* bsrc = g_embT2 + kn * 32;
            for (int t = tid; t < 2048; t += 256) {
                int r = t >> 3, c4 = t & 7;
                cp16(bb + sw128(r * 128 + c4 * 16), bsrc + (size_t)r * 3072 + c4 * 4);
            }
            cp_commit();
        }
    }
    MBAR_WAIT(sbase + 8, (uint32_t)(95 & 1));
    TC_FENCE_AFTER();

    // epilogue: D[128 lanes][256 cols] -> q, loss partial
    {
        int wg = tid >> 7, w4 = (tid >> 5) & 3, lane = tid & 31;
        int row = row0 + w4 * 32 + lane;
        float lp = 0.f;
#pragma unroll 1
        for (int b = 0; b < 4; ++b) {
            uint32_t r[32];
            LDTM32(r, tmem + wg * 128 + b * 32);
            TC_WAIT_LD();
            int cb = wg * 128 + b * 32;
            float4* qp = (float4*)(out + OFF_Q + (size_t)row * ND + cb);
            const float4* lt = (const float4*)(lat + (size_t)row * ND + cb);
#pragma unroll
            for (int c4 = 0; c4 < 8; ++c4) {
                float4 q = make_float4(__uint_as_float(r[c4 * 4 + 0]),
                                       __uint_as_float(r[c4 * 4 + 1]),
                                       __uint_as_float(r[c4 * 4 + 2]),
                                       __uint_as_float(r[c4 * 4 + 3]));
                float4 l = lt[c4];
                qp[c4] = q;
                float d0 = q.x - l.x, d1 = q.y - l.y, d2 = q.z - l.z, d3 = q.w - l.w;
                lp = fmaf(d0, d0, lp); lp = fmaf(d1, d1, lp);
                lp = fmaf(d2, d2, lp); lp = fmaf(d3, d3, lp);
            }
        }
        TC_FENCE_BEFORE();
#pragma unroll
        for (int off = 16; off; off >>= 1) lp += __shfl_xor_sync(0xffffffffu, lp, off);
        float* red = (float*)(smem + 16);
        if ((tid & 31) == 0) red[tid >> 5] = lp;
        __syncthreads();
        if (tid == 0) {
            float s = 0.f;
            for (int ww = 0; ww < 8; ++ww) s += red[ww];
            g_ploss[blockIdx.x] = s;
        }
    }
    if (tid == 0) MBAR_INVAL(sbase + 8);
    __syncthreads();
    if (wid == 0) TC_DEALLOC(tmem, 512);
#else
    // ---------------- FFMA fallback (R4 GEMM2 structure) ----------------
    extern __shared__ float smf[];
    float* sE  = smf;           // 2 x 8192 floats
    float* sPb = smf + 16384;   // 1024 floats (P block 32x32)
    __shared__ float red8[8];
    const int tid = threadIdx.x, w = tid >> 5, lane = tid & 31;
    const int row0 = blockIdx.x * 128;
    float lsum = 0.f;

    for (int st = 0; st < 4; ++st) {
        const int r0 = row0 + st * 32;
        const float* pbase = out + OFF_P + (size_t)r0 * NK;

        float qacc[4][8];
#pragma unroll
        for (int i = 0; i < 4; ++i)
#pragma unroll
            for (int m = 0; m < 8; ++m) qacc[i][m] = 0.f;

        for (int i = tid; i < 2048; i += 256) cp16(sE + i * 4, emb + i * 4);
        cp_commit();

#pragma unroll 1
        for (int ch = 0; ch < 32; ++ch) {
            if (ch < 31) {
                const float* src = emb + (size_t)(ch + 1) * 32 * ND;
                float* dst = sE + ((ch + 1) & 1) * 8192;
                for (int i = tid; i < 2048; i += 256) cp16(dst + i * 4, src + i * 4);
                cp_commit();
                cp_wait1();
            } else {
                cp_wait0();
            }
            __syncthreads();
            for (int i = tid; i < 1024; i += 256) {
                int r = i >> 5, c = i & 31;
                sPb[i] = pbase[(size_t)r * NK + ch * 32 + c];
            }
            __syncthreads();

            const float* bp = sE + (ch & 1) * 8192;
#pragma unroll 4
            for (int c = 0; c < 32; ++c) {
                float p0 = sPb[(w * 4 + 0) * 32 + c];
                float p1 = sPb[(w * 4 + 1) * 32 + c];
                float p2 = sPb[(w * 4 + 2) * 32 + c];
                float p3 = sPb[(w * 4 + 3) * 32 + c];
                const float* er = bp + c * ND + lane;
#pragma unroll
                for (int m = 0; m < 8; ++m) {
                    float ev = er[32 * m];
                    qacc[0][m] = fmaf(p0, ev, qacc[0][m]);
                    qacc[1][m] = fmaf(p1, ev, qacc[1][m]);
                    qacc[2][m] = fmaf(p2, ev, qacc[2][m]);
                    qacc[3][m] = fmaf(p3, ev, qacc[3][m]);
                }
            }
            __syncthreads();
        }
#pragma unroll
        for (int i = 0; i < 4; ++i) {
            int row = r0 + w * 4 + i;
#pragma unroll
            for (int m = 0; m < 8; ++m) {
                int d = lane + 32 * m;
                float qv = qacc[i][m];
                out[OFF_Q + (size_t)row * ND + d] = qv;
                float dz = qv - lat[(size_t)row * ND + d];
                lsum = fmaf(dz, dz, lsum);
            }
        }
        __syncthreads();
    }
#pragma unroll
    for (int off = 16; off; off >>= 1) lsum += __shfl_xor_sync(0xffffffffu, lsum, off);
    if (lane == 0) red8[w] = lsum;
    __syncthreads();
    if (tid == 0) {
        float s = 0.f;
        for (int ww = 0; ww < 8; ++ww) s += red8[ww];
        g_ploss[blockIdx.x] = s;
    }
#endif
}

// ---------------- stage-2 avg_probs reduction ----------------
__global__ void k_red() {
    int g = blockIdx.x;
    for (int c = threadIdx.x; c < NK; c += 256) {
        float s = 0.f;
        for (int r = 0; r < 64; ++r) s += g_pavg[(size_t)(g * 64 + r) * NK + c];
        g_pavg2[g * NK + c] = s;
    }
}

// ---------------- finalize scalars ----------------
__global__ void k_fin(float* __restrict__ out) {
    __shared__ float red[1024];
    int t = threadIdx.x;

    float a = 0.f;
    for (int gg = 0; gg < 32; ++gg) a += g_pavg2[gg * NK + t];
    a *= (1.0f / 65536.0f);
    red[t] = -a * logf(a + 1e-10f);
    __syncthreads();
    for (int s = 512; s; s >>= 1) { if (t < s) red[t] += red[t + s]; __syncthreads(); }
    float ent = red[0];
    __syncthreads();

    red[t] = (t < 512) ? g_ploss[t] : 0.f;
    __syncthreads();
    for (int s = 512; s; s >>= 1) { if (t < s) red[t] += red[t + s]; __syncthreads(); }
    float mse = red[0] * (1.0f / 16777216.0f);
    float vq  = __fadd_rn(__fmul_rn(mse, 0.25f), mse);
    __syncthreads();

    red[t] = g_pmind[t] + g_pmind[t + 1024];
    __syncthreads();
    for (int s = 512; s; s >>= 1) { if (t < s) red[t] += red[t + s]; __syncthreads(); }
    float cm = red[0] * (1.0f / 65536.0f);

    if (t == 0) {
        out[OFF_VQ]  = vq;
        out[OFF_ENT] = ent;
        out[OFF_CM]  = cm;
    }
}

// ---------------- launch ----------------
extern "C" void kernel_launch(void* const* d_in, const int* in_sizes, int n_in,
                              void* d_out, int out_size) {
    const float* lat = (const float*)d_in[0];
    const float* emb = (const float*)d_in[1];
    float* out = (float*)d_out;

    cudaFuncSetAttribute(k_gemm1, cudaFuncAttributeMaxDynamicSharedMemorySize, G1_SMEM);
    cudaFuncSetAttribute(k_gemm2, cudaFuncAttributeMaxDynamicSharedMemorySize, G2_SMEM);

    k_prep2<<<1024, 256>>>(emb);
    k_ee<<<4, 256>>>(emb);
    k_gemm1<<<512, 256, G1_SMEM>>>(lat, emb);
    k_soft<<<2048, 256>>>(lat, emb, out);
    k_gemm2<<<512, 256, G2_SMEM>>>(lat, emb, out);
    k_red<<<32, 256>>>();
    k_fin<<<1, 1024>>>(out);
}